// round 1
// baseline (speedup 1.0000x reference)
#include <cuda_runtime.h>
#include <cstdint>

// Problem constants
#define MDW   4
#define UDIM  9          // 2*MD+1
#define NB    2
#define NC    128
#define NH    64
#define NW    64
#define NF    16
#define NHW   4096
#define OUT1_ELEMS (NB*NF*4*NHW)        // 524288
#define WARP_ELEMS (NB*NC*NHW)          // 1048576

// cvol scratch: [b*F][uv=du*9+dv][h][w]  (42.5 MB)
__device__ float g_cvol[NB*NF*81*NHW];

typedef unsigned long long u64;

__device__ __forceinline__ u64 pk2(float x, float y) {
    u64 r; asm("mov.b64 %0, {%1,%2};" : "=l"(r) : "f"(x), "f"(y)); return r;
}
__device__ __forceinline__ float2 upk(u64 v) {
    float2 f; asm("mov.b64 {%0,%1}, %2;" : "=f"(f.x), "=f"(f.y) : "l"(v)); return f;
}
__device__ __forceinline__ u64 ffma2(u64 a, u64 b, u64 c) {
    u64 d; asm("fma.rn.f32x2 %0, %1, %2, %3;" : "=l"(d) : "l"(a), "l"(b), "l"(c)); return d;
}

// ---------------------------------------------------------------------------
// Kernel A: cost volume + channel projection
// grid (dv=9, h=64, b=2), block 288 (9 warps, warp <-> du)
// smem: P[9][32][32] u64 | w2[128][16] u64 | ref[128][64] f32 | tar[128][72] f32
// ---------------------------------------------------------------------------
#define SMEM_A_BYTES (9*32*32*8 + 128*16*8 + 128*64*4 + 128*72*4)

__global__ __launch_bounds__(288) void cvol_kernel(
    const float* __restrict__ ref, const float* __restrict__ tar,
    const float* __restrict__ pw)
{
    extern __shared__ char smem[];
    u64*   Pu   = (u64*)smem;                 // [9][32 c][32 pairs]
    u64*   w2   = Pu + 9*32*32;               // [128][16] duplicated pairs
    float* refs = (float*)(w2 + 128*16);      // [128][64]
    float* tars = refs + 128*64;              // [128][72], cols -4..67 zero-padded

    const int dv = blockIdx.x, h = blockIdx.y, b = blockIdx.z;
    const int tid = threadIdx.x;
    const int hr = h + dv - MDW;
    const bool rowok = (hr >= 0) && (hr < NH);

    for (int i = tid; i < 128*64; i += 288) {
        int c = i >> 6, x = i & 63;
        refs[i] = ref[((b*NC + c) << 12) + (h << 6) + x];
    }
    for (int i = tid; i < 128*72; i += 288) {
        int c = i / 72, k = i - c*72;
        int x = k - MDW;
        float v = 0.f;
        if (rowok && x >= 0 && x < NW) v = tar[((b*NC + c) << 12) + (hr << 6) + x];
        tars[i] = v;
    }
    for (int i = tid; i < 128*16; i += 288) {
        int c = i >> 4, f = i & 15;
        float v = pw[f*NC + c];
        w2[i] = pk2(v, v);
    }
    __syncthreads();

    const int du   = tid >> 5;      // warp id = du (0..8)
    const int lane = tid & 31;
    const int fg   = lane >> 4;     // 0..1 -> f in [fg*8, fg*8+8)
    const int pg   = lane & 15;     // pair-group -> pixels 4*pg..4*pg+3

    u64 acc[8][2];
#pragma unroll
    for (int j = 0; j < 8; j++) { acc[j][0] = 0ull; acc[j][1] = 0ull; }

    u64* Pw = Pu + du*32*32;

    for (int k0 = 0; k0 < 128; k0 += 32) {
        // produce P chunk (each lane: pixels 2*lane, 2*lane+1)
#pragma unroll 4
        for (int c = 0; c < 32; c++) {
            int cc = k0 + c;
            float r0 = refs[cc*64 + 2*lane];
            float r1 = refs[cc*64 + 2*lane + 1];
            float t0 = tars[cc*72 + 2*lane + du];
            float t1 = tars[cc*72 + 2*lane + 1 + du];
            float p0 = r0 * t0; p0 = fmaxf(p0, 0.1f*p0);
            float p1 = r1 * t1; p1 = fmaxf(p1, 0.1f*p1);
            Pw[c*32 + lane] = pk2(p0, p1);
        }
        __syncwarp();
        // GEMM accumulate: 8 f x 4 pixels per thread, packed f32x2
#pragma unroll 4
        for (int c = 0; c < 32; c++) {
            int cc = k0 + c;
            ulonglong2 pA = *(const ulonglong2*)&Pw[c*32 + 2*pg];
            const ulonglong2* wv = (const ulonglong2*)&w2[cc*16 + fg*8];
            u64 wr[8];
            ulonglong2 t;
            t = wv[0]; wr[0] = t.x; wr[1] = t.y;
            t = wv[1]; wr[2] = t.x; wr[3] = t.y;
            t = wv[2]; wr[4] = t.x; wr[5] = t.y;
            t = wv[3]; wr[6] = t.x; wr[7] = t.y;
#pragma unroll
            for (int j = 0; j < 8; j++) {
                acc[j][0] = ffma2(pA.x, wr[j], acc[j][0]);
                acc[j][1] = ffma2(pA.y, wr[j], acc[j][1]);
            }
        }
        __syncwarp();
    }

    const int uv = du*9 + dv;
#pragma unroll
    for (int j = 0; j < 8; j++) {
        int f  = fg*8 + j;
        int bf = b*NF + f;
        float2 a0 = upk(acc[j][0]);
        float2 a1 = upk(acc[j][1]);
        float4 o = make_float4(a0.x, a0.y, a1.x, a1.y);
        *(float4*)&g_cvol[((bf*81 + uv) << 12) + (h << 6) + 4*pg] = o;
    }
}

// ---------------------------------------------------------------------------
// Kernel B: flow_reg (argmax -> 7x7 mask -> masked softmax -> soft-argmax + entropies)
// one thread per (b*F, pixel); 131072 threads
// ---------------------------------------------------------------------------
__global__ __launch_bounds__(256) void flowreg_kernel(float* __restrict__ out)
{
    int g = blockIdx.x * 256 + threadIdx.x;     // 0..131071
    int bf = g >> 12, pix = g & 4095;
    const float* base = g_cvol + ((bf*81) << 12) + pix;

    float v[81];
#pragma unroll
    for (int i = 0; i < 81; i++) v[i] = base[i << 12];

    float m = v[0]; int am = 0;
#pragma unroll
    for (int i = 1; i < 81; i++) if (v[i] > m) { m = v[i]; am = i; }
    int ub = am / 9, vb = am - 9*(am/9);

    float S = 0.f, T = 0.f, Sx = 0.f, Sy = 0.f, gS = 0.f, gT = 0.f;
#pragma unroll
    for (int u = 0; u < 9; u++) {
#pragma unroll
        for (int w = 0; w < 9; w++) {
            float d = v[u*9 + w] - m;
            float e = __expf(d);
            gS += e; gT += e*d;
            bool inm = (abs(u - ub) <= 3) && (abs(w - vb) <= 3);
            if (inm) {
                S += e; T += e*d;
                Sx += e * (float)(u - 4);
                Sy += e * (float)(w - 4);
            }
        }
    }
    float inv  = 1.f / S;
    float ginv = 1.f / gS;
    float outx = Sx * inv;
    float outy = Sy * inv;
    float lent = (logf(S)  - T  * inv ) * 0.25694936f;   // 1/log(49)
    float gent = (logf(gS) - gT * ginv) * 0.22756237f;   // 1/log(81)

    out[(bf*4 + 0)*NHW + pix] = outx;
    out[(bf*4 + 1)*NHW + pix] = outy;
    out[(bf*4 + 2)*NHW + pix] = lent;
    out[(bf*4 + 3)*NHW + pix] = gent;
}

// ---------------------------------------------------------------------------
// Kernel C: bilinear backward warp of tar_feat by flow (hypothesis f=0)
// one thread per output element (b,c,y,x); 1048576 threads
// ---------------------------------------------------------------------------
__global__ __launch_bounds__(256) void warp_kernel(
    const float* __restrict__ tar, float* __restrict__ out)
{
    int g = blockIdx.x * 256 + threadIdx.x;       // 0..1048575
    int x = g & 63, y = (g >> 6) & 63, c = (g >> 12) & 127, b = g >> 19;

    const float* fbase = out + b*(NF*4*NHW) + (y << 6) + x;  // bf = b*16+0, ch 0/1
    float fx = fbase[0];
    float fy = fbase[NHW];

    float px = (float)x + fx;
    float py = (float)y + fy;
    bool inb = (fabsf(2.0f*px/63.0f - 1.0f) < 1.0f) &&
               (fabsf(2.0f*py/63.0f - 1.0f) < 1.0f);

    float x0f = floorf(px), y0f = floorf(py);
    float wx = px - x0f, wy = py - y0f;
    int x0 = (int)x0f, y0 = (int)y0f;

    const float* img = tar + ((b*NC + c) << 12);
    float s = 0.f;
#pragma unroll
    for (int dy = 0; dy < 2; dy++) {
#pragma unroll
        for (int dx = 0; dx < 2; dx++) {
            int xi = x0 + dx, yi = y0 + dy;
            bool ok = (xi >= 0) && (xi < NW) && (yi >= 0) && (yi < NH);
            float wgt = (dx ? wx : 1.f - wx) * (dy ? wy : 1.f - wy);
            int xc = min(max(xi, 0), NW-1), yc = min(max(yi, 0), NH-1);
            s += img[(yc << 6) + xc] * (ok ? wgt : 0.f);
        }
    }
    out[OUT1_ELEMS + g] = s * (inb ? 1.f : 0.f);
}

// ---------------------------------------------------------------------------
extern "C" void kernel_launch(void* const* d_in, const int* in_sizes, int n_in,
                              void* d_out, int out_size)
{
    const float* ref = (const float*)d_in[0];
    const float* tar = (const float*)d_in[1];
    const float* pw  = (const float*)d_in[2];
    float* out = (float*)d_out;

    cudaFuncSetAttribute(cvol_kernel,
                         cudaFuncAttributeMaxDynamicSharedMemorySize, SMEM_A_BYTES);

    dim3 gA(UDIM, NH, NB);
    cvol_kernel<<<gA, 288, SMEM_A_BYTES>>>(ref, tar, pw);
    flowreg_kernel<<<(NB*NF*NHW)/256, 256>>>(out);
    warp_kernel<<<WARP_ELEMS/256, 256>>>(tar, out);
}

// round 2
// speedup vs baseline: 1.3341x; 1.3341x over previous
#include <cuda_runtime.h>
#include <cstdint>

// Problem constants
#define MDW   4
#define UDIM  9          // 2*MD+1
#define NB    2
#define NC    128
#define NH    64
#define NW    64
#define NF    16
#define NHW   4096
#define OUT1_ELEMS (NB*NF*4*NHW)        // 524288
#define WARP_ELEMS (NB*NC*NHW)          // 1048576

// cvol scratch: [b*F][uv=du*9+dv][h][w]  (42.5 MB)
__device__ float g_cvol[NB*NF*81*NHW];

typedef unsigned long long u64;

__device__ __forceinline__ u64 pk2(float x, float y) {
    u64 r; asm("mov.b64 %0, {%1,%2};" : "=l"(r) : "f"(x), "f"(y)); return r;
}
__device__ __forceinline__ float2 upk(u64 v) {
    float2 f; asm("mov.b64 {%0,%1}, %2;" : "=f"(f.x), "=f"(f.y) : "l"(v)); return f;
}
__device__ __forceinline__ u64 ffma2(u64 a, u64 b, u64 c) {
    u64 d; asm("fma.rn.f32x2 %0, %1, %2, %3;" : "=l"(d) : "l"(a), "l"(b), "l"(c)); return d;
}

// ---------------------------------------------------------------------------
// Kernel A: cost volume + channel projection
// grid (dv=9, h=64, b=2), block 288 (9 warps, warp <-> du), 2 blocks/SM
// smem: P[9][8][32] u64 | w2[128][16] u64 | ref[128][64] f32 | tar[128][72] f32
//       18432 + 16384 + 32768 + 36864 = 104448 B  -> 2 CTAs/SM
// ---------------------------------------------------------------------------
#define KCH 8
#define SMEM_A_BYTES (9*KCH*32*8 + 128*16*8 + 128*64*4 + 128*72*4)

__global__ __launch_bounds__(288, 2) void cvol_kernel(
    const float* __restrict__ ref, const float* __restrict__ tar,
    const float* __restrict__ pw)
{
    extern __shared__ char smem[];
    u64*   Pu   = (u64*)smem;                 // [9][KCH][32 pairs]
    u64*   w2   = Pu + 9*KCH*32;              // [128][16] duplicated pairs
    float* refs = (float*)(w2 + 128*16);      // [128][64]
    float* tars = refs + 128*64;              // [128][72], cols -4..67 zero-padded

    const int dv = blockIdx.x, h = blockIdx.y, b = blockIdx.z;
    const int tid = threadIdx.x;
    const int hr = h + dv - MDW;
    const bool rowok = (hr >= 0) && (hr < NH);

    for (int i = tid; i < 128*64; i += 288) {
        int c = i >> 6, x = i & 63;
        refs[i] = ref[((b*NC + c) << 12) + (h << 6) + x];
    }
    for (int i = tid; i < 128*72; i += 288) {
        int c = i / 72, k = i - c*72;
        int x = k - MDW;
        float v = 0.f;
        if (rowok && x >= 0 && x < NW) v = tar[((b*NC + c) << 12) + (hr << 6) + x];
        tars[i] = v;
    }
    for (int i = tid; i < 128*16; i += 288) {
        int c = i >> 4, f = i & 15;
        float v = pw[f*NC + c];
        w2[i] = pk2(v, v);
    }
    __syncthreads();

    const int du   = tid >> 5;      // warp id = du (0..8)
    const int lane = tid & 31;
    const int fg   = lane >> 4;     // 0..1 -> f in [fg*8, fg*8+8)
    const int pg   = lane & 15;     // pair-group -> pixels 4*pg..4*pg+3

    u64 acc[8][2];
#pragma unroll
    for (int j = 0; j < 8; j++) { acc[j][0] = 0ull; acc[j][1] = 0ull; }

    u64* Pw = Pu + du*KCH*32;

    for (int k0 = 0; k0 < 128; k0 += KCH) {
        // produce P chunk (each lane: pixels 2*lane, 2*lane+1)
#pragma unroll
        for (int c8 = 0; c8 < KCH; c8++) {
            int cc = k0 + c8;
            float2 r = *(const float2*)&refs[cc*64 + 2*lane];
            float t0 = tars[cc*72 + 2*lane + du];
            float t1 = tars[cc*72 + 2*lane + 1 + du];
            float p0 = r.x * t0; p0 = fmaxf(p0, 0.1f*p0);
            float p1 = r.y * t1; p1 = fmaxf(p1, 0.1f*p1);
            Pw[c8*32 + lane] = pk2(p0, p1);
        }
        __syncwarp();
        // GEMM accumulate: 8 f x 4 pixels per thread, packed f32x2
#pragma unroll
        for (int c8 = 0; c8 < KCH; c8++) {
            int cc = k0 + c8;
            ulonglong2 pA = *(const ulonglong2*)&Pw[c8*32 + 2*pg];
            const ulonglong2* wv = (const ulonglong2*)&w2[cc*16 + fg*8];
            u64 wr[8];
            ulonglong2 t;
            t = wv[0]; wr[0] = t.x; wr[1] = t.y;
            t = wv[1]; wr[2] = t.x; wr[3] = t.y;
            t = wv[2]; wr[4] = t.x; wr[5] = t.y;
            t = wv[3]; wr[6] = t.x; wr[7] = t.y;
#pragma unroll
            for (int j = 0; j < 8; j++) {
                acc[j][0] = ffma2(pA.x, wr[j], acc[j][0]);
                acc[j][1] = ffma2(pA.y, wr[j], acc[j][1]);
            }
        }
        __syncwarp();
    }

    const int uv = du*9 + dv;
#pragma unroll
    for (int j = 0; j < 8; j++) {
        int f  = fg*8 + j;
        int bf = b*NF + f;
        float2 a0 = upk(acc[j][0]);
        float2 a1 = upk(acc[j][1]);
        float4 o = make_float4(a0.x, a0.y, a1.x, a1.y);
        *(float4*)&g_cvol[((bf*81 + uv) << 12) + (h << 6) + 4*pg] = o;
    }
}

// ---------------------------------------------------------------------------
// Kernel B: flow_reg (argmax -> 7x7 mask -> masked softmax -> soft-argmax + entropies)
// one thread per (b*F, pixel); 131072 threads
// ---------------------------------------------------------------------------
__global__ __launch_bounds__(256) void flowreg_kernel(float* __restrict__ out)
{
    int g = blockIdx.x * 256 + threadIdx.x;     // 0..131071
    int bf = g >> 12, pix = g & 4095;
    const float* base = g_cvol + ((bf*81) << 12) + pix;

    float v[81];
#pragma unroll
    for (int i = 0; i < 81; i++) v[i] = base[i << 12];

    float m = v[0]; int am = 0;
#pragma unroll
    for (int i = 1; i < 81; i++) if (v[i] > m) { m = v[i]; am = i; }
    int ub = am / 9, vb = am - 9*(am/9);

    float S = 0.f, T = 0.f, Sx = 0.f, Sy = 0.f, gS = 0.f, gT = 0.f;
#pragma unroll
    for (int u = 0; u < 9; u++) {
#pragma unroll
        for (int w = 0; w < 9; w++) {
            float d = v[u*9 + w] - m;
            float e = __expf(d);
            gS += e; gT += e*d;
            bool inm = (abs(u - ub) <= 3) && (abs(w - vb) <= 3);
            if (inm) {
                S += e; T += e*d;
                Sx += e * (float)(u - 4);
                Sy += e * (float)(w - 4);
            }
        }
    }
    float inv  = 1.f / S;
    float ginv = 1.f / gS;
    float outx = Sx * inv;
    float outy = Sy * inv;
    float lent = (logf(S)  - T  * inv ) * 0.25694936f;   // 1/log(49)
    float gent = (logf(gS) - gT * ginv) * 0.22756237f;   // 1/log(81)

    out[(bf*4 + 0)*NHW + pix] = outx;
    out[(bf*4 + 1)*NHW + pix] = outy;
    out[(bf*4 + 2)*NHW + pix] = lent;
    out[(bf*4 + 3)*NHW + pix] = gent;
}

// ---------------------------------------------------------------------------
// Kernel C: bilinear backward warp of tar_feat by flow (hypothesis f=0)
// one thread per output element (b,c,y,x); 1048576 threads
// ---------------------------------------------------------------------------
__global__ __launch_bounds__(256) void warp_kernel(
    const float* __restrict__ tar, float* __restrict__ out)
{
    int g = blockIdx.x * 256 + threadIdx.x;       // 0..1048575
    int x = g & 63, y = (g >> 6) & 63, c = (g >> 12) & 127, b = g >> 19;

    const float* fbase = out + b*(NF*4*NHW) + (y << 6) + x;  // bf = b*16+0, ch 0/1
    float fx = fbase[0];
    float fy = fbase[NHW];

    float px = (float)x + fx;
    float py = (float)y + fy;
    bool inb = (fabsf(2.0f*px/63.0f - 1.0f) < 1.0f) &&
               (fabsf(2.0f*py/63.0f - 1.0f) < 1.0f);

    float x0f = floorf(px), y0f = floorf(py);
    float wx = px - x0f, wy = py - y0f;
    int x0 = (int)x0f, y0 = (int)y0f;

    const float* img = tar + ((b*NC + c) << 12);
    float s = 0.f;
#pragma unroll
    for (int dy = 0; dy < 2; dy++) {
#pragma unroll
        for (int dx = 0; dx < 2; dx++) {
            int xi = x0 + dx, yi = y0 + dy;
            bool ok = (xi >= 0) && (xi < NW) && (yi >= 0) && (yi < NH);
            float wgt = (dx ? wx : 1.f - wx) * (dy ? wy : 1.f - wy);
            int xc = min(max(xi, 0), NW-1), yc = min(max(yi, 0), NH-1);
            s += img[(yc << 6) + xc] * (ok ? wgt : 0.f);
        }
    }
    out[OUT1_ELEMS + g] = s * (inb ? 1.f : 0.f);
}

// ---------------------------------------------------------------------------
extern "C" void kernel_launch(void* const* d_in, const int* in_sizes, int n_in,
                              void* d_out, int out_size)
{
    const float* ref = (const float*)d_in[0];
    const float* tar = (const float*)d_in[1];
    const float* pw  = (const float*)d_in[2];
    float* out = (float*)d_out;

    cudaFuncSetAttribute(cvol_kernel,
                         cudaFuncAttributeMaxDynamicSharedMemorySize, SMEM_A_BYTES);

    dim3 gA(UDIM, NH, NB);
    cvol_kernel<<<gA, 288, SMEM_A_BYTES>>>(ref, tar, pw);
    flowreg_kernel<<<(NB*NF*NHW)/256, 256>>>(out);
    warp_kernel<<<WARP_ELEMS/256, 256>>>(tar, out);
}

// round 3
// speedup vs baseline: 1.7468x; 1.3093x over previous
#include <cuda_runtime.h>
#include <cstdint>

// Problem constants
#define MDW   4
#define UDIM  9          // 2*MD+1
#define NB    2
#define NC    128
#define NH    64
#define NW    64
#define NF    16
#define NHW   4096
#define OUT1_ELEMS (NB*NF*4*NHW)        // 524288
#define WARP_ELEMS (NB*NC*NHW)          // 1048576

// cvol scratch: [b*F][uv=du*9+dv][h][w]  (42.5 MB)
__device__ float g_cvol[NB*NF*81*NHW];

typedef unsigned long long u64;

__device__ __forceinline__ u64 pk2(float x, float y) {
    u64 r; asm("mov.b64 %0, {%1,%2};" : "=l"(r) : "f"(x), "f"(y)); return r;
}
__device__ __forceinline__ float2 upk(u64 v) {
    float2 f; asm("mov.b64 {%0,%1}, %2;" : "=f"(f.x), "=f"(f.y) : "l"(v)); return f;
}
__device__ __forceinline__ u64 ffma2(u64 a, u64 b, u64 c) {
    u64 d; asm("fma.rn.f32x2 %0, %1, %2, %3;" : "=l"(d) : "l"(a), "l"(b), "l"(c)); return d;
}
__device__ __forceinline__ u64 fmul2(u64 a, u64 b) {
    u64 d; asm("mul.rn.f32x2 %0, %1, %2;" : "=l"(d) : "l"(a), "l"(b)); return d;
}

// ---------------------------------------------------------------------------
// Kernel A: cost volume + channel projection (no P staging:
// lrelu(p) = 0.55*p + 0.45*|p| => bilinear form, each thread computes its own q)
// grid (dv=9, h=64, b=2), block 288 (9 warps, warp <-> du), 2 blocks/SM
// lane <-> pixels (l, l+32); f32x2 pairs over (f, f+1).
// smem: refs[128][64] f32 | tars[128][72] f32 | ws[128][16] f32  = 76 KB
// ---------------------------------------------------------------------------
#define SMEM_A_BYTES (128*64*4 + 128*72*4 + 128*16*4)

__global__ __launch_bounds__(288, 2) void cvol_kernel(
    const float* __restrict__ ref, const float* __restrict__ tar,
    const float* __restrict__ pw)
{
    extern __shared__ char smem[];
    float* refs = (float*)smem;              // [128][64]
    float* tars = refs + 128*64;             // [128][72], cols -4..67 zero-padded
    float* ws   = tars + 128*72;             // [128][16]  (transposed pw)

    const int dv = blockIdx.x, h = blockIdx.y, b = blockIdx.z;
    const int tid = threadIdx.x;
    const int hr = h + dv - MDW;
    const bool rowok = (hr >= 0) && (hr < NH);

    // fill refs (vectorized float4)
    for (int i = tid; i < 128*16; i += 288) {
        int c = i >> 4, xq = i & 15;
        *(float4*)&refs[c*64 + 4*xq] =
            *(const float4*)&ref[((b*NC + c) << 12) + (h << 6) + 4*xq];
    }
    // fill tars (zero-padded borders)
    for (int i = tid; i < 128*72; i += 288) {
        int c = i / 72, k = i - c*72;
        int x = k - MDW;
        float v = 0.f;
        if (rowok && x >= 0 && x < NW) v = tar[((b*NC + c) << 12) + (hr << 6) + x];
        tars[i] = v;
    }
    // fill ws transposed: ws[c][f] = pw[f][c]
    for (int i = tid; i < 128*16; i += 288) {
        int c = i >> 4, f = i & 15;
        ws[i] = pw[f*NC + c];
    }
    __syncthreads();

    const int du   = tid >> 5;      // warp id = du (0..8)
    const int lane = tid & 31;

    const float* refp = refs + lane;              // pixel l   (stride 64/c)
    const float* tarp = tars + lane + du;         // pixel l+du-4 (stride 72/c)
    const ulonglong2* wp = (const ulonglong2*)ws; // [c][4] of ((f,f+1) pairs)

    const u64 C55  = 0x3F0CCCCD3F0CCCCDull;   // (0.55f, 0.55f)
    const u64 C45  = 0x3EE666663EE66666ull;   // (0.45f, 0.45f)
    const u64 MABS = 0x7FFFFFFF7FFFFFFFull;

    u64 acc[16];                    // [fpair 0..7][pix 0..1]
#pragma unroll
    for (int i = 0; i < 16; i++) acc[i] = 0ull;

#pragma unroll 8
    for (int c = 0; c < 128; c++) {
        float r0 = refp[c*64];
        float r1 = refp[c*64 + 32];
        float t0 = tarp[c*72];
        float t1 = tarp[c*72 + 32];
        u64 p = fmul2(pk2(r0, r1), pk2(t0, t1));
        u64 q = ffma2(p & MABS, C45, fmul2(p, C55));   // lrelu(p,0.1)
        float2 qf = upk(q);
        u64 qa = pk2(qf.x, qf.x);   // pixel l      dup
        u64 qb = pk2(qf.y, qf.y);   // pixel l+32   dup
        ulonglong2 w0 = wp[c*4 + 0];
        ulonglong2 w1 = wp[c*4 + 1];
        ulonglong2 w2 = wp[c*4 + 2];
        ulonglong2 w3 = wp[c*4 + 3];
        acc[ 0] = ffma2(qa, w0.x, acc[ 0]);  acc[ 1] = ffma2(qb, w0.x, acc[ 1]);
        acc[ 2] = ffma2(qa, w0.y, acc[ 2]);  acc[ 3] = ffma2(qb, w0.y, acc[ 3]);
        acc[ 4] = ffma2(qa, w1.x, acc[ 4]);  acc[ 5] = ffma2(qb, w1.x, acc[ 5]);
        acc[ 6] = ffma2(qa, w1.y, acc[ 6]);  acc[ 7] = ffma2(qb, w1.y, acc[ 7]);
        acc[ 8] = ffma2(qa, w2.x, acc[ 8]);  acc[ 9] = ffma2(qb, w2.x, acc[ 9]);
        acc[10] = ffma2(qa, w2.y, acc[10]);  acc[11] = ffma2(qb, w2.y, acc[11]);
        acc[12] = ffma2(qa, w3.x, acc[12]);  acc[13] = ffma2(qb, w3.x, acc[13]);
        acc[14] = ffma2(qa, w3.y, acc[14]);  acc[15] = ffma2(qb, w3.y, acc[15]);
    }

    // epilogue: acc[2*fp+px] = ((f=2fp, f=2fp+1) at pixel (px ? lane+32 : lane))
    const int uv = du*9 + dv;
    const int pbase = (h << 6) + lane;
#pragma unroll
    for (int fp = 0; fp < 8; fp++) {
        float2 a0 = upk(acc[2*fp]);       // pixel lane
        float2 a1 = upk(acc[2*fp + 1]);   // pixel lane+32
        int f0 = 2*fp, f1 = 2*fp + 1;
        float* o0 = &g_cvol[(((b*NF + f0)*81 + uv) << 12) + pbase];
        float* o1 = &g_cvol[(((b*NF + f1)*81 + uv) << 12) + pbase];
        o0[0]  = a0.x;  o0[32] = a1.x;
        o1[0]  = a0.y;  o1[32] = a1.y;
    }
}

// ---------------------------------------------------------------------------
// Kernel B: flow_reg (argmax -> 7x7 mask -> masked softmax -> soft-argmax + entropies)
// one thread per (b*F, pixel); 131072 threads
// ---------------------------------------------------------------------------
__global__ __launch_bounds__(256) void flowreg_kernel(float* __restrict__ out)
{
    int g = blockIdx.x * 256 + threadIdx.x;     // 0..131071
    int bf = g >> 12, pix = g & 4095;
    const float* base = g_cvol + ((bf*81) << 12) + pix;

    float v[81];
#pragma unroll
    for (int i = 0; i < 81; i++) v[i] = base[i << 12];

    float m = v[0]; int am = 0;
#pragma unroll
    for (int i = 1; i < 81; i++) if (v[i] > m) { m = v[i]; am = i; }
    int ub = am / 9, vb = am - 9*(am/9);

    float S = 0.f, T = 0.f, Sx = 0.f, Sy = 0.f, gS = 0.f, gT = 0.f;
#pragma unroll
    for (int u = 0; u < 9; u++) {
#pragma unroll
        for (int w = 0; w < 9; w++) {
            float d = v[u*9 + w] - m;
            float e = __expf(d);
            gS += e; gT += e*d;
            bool inm = (abs(u - ub) <= 3) && (abs(w - vb) <= 3);
            if (inm) {
                S += e; T += e*d;
                Sx += e * (float)(u - 4);
                Sy += e * (float)(w - 4);
            }
        }
    }
    float inv  = 1.f / S;
    float ginv = 1.f / gS;
    float outx = Sx * inv;
    float outy = Sy * inv;
    float lent = (logf(S)  - T  * inv ) * 0.25694936f;   // 1/log(49)
    float gent = (logf(gS) - gT * ginv) * 0.22756237f;   // 1/log(81)

    out[(bf*4 + 0)*NHW + pix] = outx;
    out[(bf*4 + 1)*NHW + pix] = outy;
    out[(bf*4 + 2)*NHW + pix] = lent;
    out[(bf*4 + 3)*NHW + pix] = gent;
}

// ---------------------------------------------------------------------------
// Kernel C: bilinear backward warp of tar_feat by flow (hypothesis f=0)
// one thread per output element (b,c,y,x); 1048576 threads
// ---------------------------------------------------------------------------
__global__ __launch_bounds__(256) void warp_kernel(
    const float* __restrict__ tar, float* __restrict__ out)
{
    int g = blockIdx.x * 256 + threadIdx.x;       // 0..1048575
    int x = g & 63, y = (g >> 6) & 63, c = (g >> 12) & 127, b = g >> 19;

    const float* fbase = out + b*(NF*4*NHW) + (y << 6) + x;  // bf = b*16+0, ch 0/1
    float fx = fbase[0];
    float fy = fbase[NHW];

    float px = (float)x + fx;
    float py = (float)y + fy;
    bool inb = (fabsf(2.0f*px/63.0f - 1.0f) < 1.0f) &&
               (fabsf(2.0f*py/63.0f - 1.0f) < 1.0f);

    float x0f = floorf(px), y0f = floorf(py);
    float wx = px - x0f, wy = py - y0f;
    int x0 = (int)x0f, y0 = (int)y0f;

    const float* img = tar + ((b*NC + c) << 12);
    float s = 0.f;
#pragma unroll
    for (int dy = 0; dy < 2; dy++) {
#pragma unroll
        for (int dx = 0; dx < 2; dx++) {
            int xi = x0 + dx, yi = y0 + dy;
            bool ok = (xi >= 0) && (xi < NW) && (yi >= 0) && (yi < NH);
            float wgt = (dx ? wx : 1.f - wx) * (dy ? wy : 1.f - wy);
            int xc = min(max(xi, 0), NW-1), yc = min(max(yi, 0), NH-1);
            s += img[(yc << 6) + xc] * (ok ? wgt : 0.f);
        }
    }
    out[OUT1_ELEMS + g] = s * (inb ? 1.f : 0.f);
}

// ---------------------------------------------------------------------------
extern "C" void kernel_launch(void* const* d_in, const int* in_sizes, int n_in,
                              void* d_out, int out_size)
{
    const float* ref = (const float*)d_in[0];
    const float* tar = (const float*)d_in[1];
    const float* pw  = (const float*)d_in[2];
    float* out = (float*)d_out;

    cudaFuncSetAttribute(cvol_kernel,
                         cudaFuncAttributeMaxDynamicSharedMemorySize, SMEM_A_BYTES);

    dim3 gA(UDIM, NH, NB);
    cvol_kernel<<<gA, 288, SMEM_A_BYTES>>>(ref, tar, pw);
    flowreg_kernel<<<(NB*NF*NHW)/256, 256>>>(out);
    warp_kernel<<<WARP_ELEMS/256, 256>>>(tar, out);
}